// round 2
// baseline (speedup 1.0000x reference)
#include <cuda_runtime.h>
#include <cuda_bf16.h>
#include <math.h>

typedef __nv_bfloat16 bf16;
#define BATCHN 65536
#define QD 256

__device__ float g_h32 [(long)BATCHN*768];
__device__ float g_tmp32[(long)BATCHN*QD];
__device__ float g_ent32[(long)BATCHN*QD];
__device__ float g_c232 [(long)BATCHN*QD];
__device__ float g_nl32 [(long)BATCHN*QD];
__device__ float g_cur32[(long)BATCHN*QD];
__device__ bf16  g_curh[(long)BATCHN*QD],  g_curl[(long)BATCHN*QD];
__device__ bf16  g_hh  [(long)BATCHN*768], g_hl  [(long)BATCHN*768];
__device__ bf16  g_tmph[(long)BATCHN*QD],  g_tmpl[(long)BATCHN*QD];
__device__ bf16  g_c2h [(long)BATCHN*QD],  g_c2l [(long)BATCHN*QD];
__device__ bf16  g_w_h[3145728], g_w_l[3145728];
__device__ float g_wf[2*256*256];
__device__ float g_battn[2*256];
__device__ float g_lin[8*256];

__device__ __forceinline__ void split2(float v, bf16& h, bf16& l){
    h = __float2bfloat16(v);
    l = __float2bfloat16(v - __bfloat162float(h));
}
__device__ __forceinline__ unsigned cvsm(const void* p){
    return (unsigned)__cvta_generic_to_shared(p);
}
__device__ __forceinline__ void ldm4(unsigned a, unsigned& r0, unsigned& r1, unsigned& r2, unsigned& r3){
    asm volatile("ldmatrix.sync.aligned.m8n8.x4.shared.b16 {%0,%1,%2,%3}, [%4];"
                 : "=r"(r0),"=r"(r1),"=r"(r2),"=r"(r3) : "r"(a));
}
__device__ __forceinline__ void mmabf(float* c, const unsigned* a, const unsigned* b){
    asm volatile("mma.sync.aligned.m16n8k16.row.col.f32.bf16.bf16.f32 "
                 "{%0,%1,%2,%3},{%4,%5,%6,%7},{%8,%9},{%0,%1,%2,%3};"
                 : "+f"(c[0]),"+f"(c[1]),"+f"(c[2]),"+f"(c[3])
                 : "r"(a[0]),"r"(a[1]),"r"(a[2]),"r"(a[3]),"r"(b[0]),"r"(b[1]));
}

#define BM 128
#define BN 128
#define BKK 32
#define LDT 40

// C[M,N] = epi(A@W + bias); A hi/lo [M][K]; W transposed hi/lo [N][K].
// EPI: 0 none, 1 silu, 2 tanh.
template<int EPI>
__global__ void __launch_bounds__(256,1) gemm_k(
    const bf16* __restrict__ Ah, const bf16* __restrict__ Al,
    const bf16* __restrict__ Bh, const bf16* __restrict__ Bl,
    const float* __restrict__ bias,
    float* __restrict__ C32, bf16* __restrict__ Ch, bf16* __restrict__ Cl,
    int K, int N)
{
    __shared__ bf16 sAh[BM*LDT], sAl[BM*LDT], sBh[BN*LDT], sBl[BN*LDT];
    const int tid=threadIdx.x, lane=tid&31, warp=tid>>5;
    const int wm=warp>>2, wn=warp&3;
    const long rowBase=(long)blockIdx.y*BM;
    const int  colBase=blockIdx.x*BN;

    float acc[4][4][4];
#pragma unroll
    for(int a=0;a<4;a++)
#pragma unroll
    for(int b=0;b<4;b++)
#pragma unroll
    for(int c=0;c<4;c++) acc[a][b][c]=0.f;

    const int r0=tid>>2, kc0=(tid&3)<<3;
    for(int k0=0;k0<K;k0+=BKK){
#pragma unroll
        for(int it=0;it<2;it++){
            int r=r0+it*64;
            long ga=(rowBase+r)*(long)K + k0 + kc0;
            long gb=((long)(colBase+r))*(long)K + k0 + kc0;
            int so=r*LDT+kc0;
            *(uint4*)(sAh+so)=*(const uint4*)(Ah+ga);
            *(uint4*)(sAl+so)=*(const uint4*)(Al+ga);
            *(uint4*)(sBh+so)=*(const uint4*)(Bh+gb);
            *(uint4*)(sBl+so)=*(const uint4*)(Bl+gb);
        }
        __syncthreads();
#pragma unroll
        for(int ks=0;ks<2;ks++){
            unsigned aH[4][4], aL[4][4], bH[4][2], bL[4][2];
            const int colo = ks*16 + ((lane>>4)<<3);
#pragma unroll
            for(int mt=0;mt<4;mt++){
                int row=wm*64+mt*16+(lane&15);
                ldm4(cvsm(sAh+row*LDT+colo), aH[mt][0],aH[mt][1],aH[mt][2],aH[mt][3]);
                ldm4(cvsm(sAl+row*LDT+colo), aL[mt][0],aL[mt][1],aL[mt][2],aL[mt][3]);
            }
#pragma unroll
            for(int np=0;np<2;np++){
                int row=wn*32+np*16+(lane&15);
                unsigned t0,t1,t2,t3;
                ldm4(cvsm(sBh+row*LDT+colo), t0,t1,t2,t3);
                bH[2*np][0]=t0; bH[2*np][1]=t2; bH[2*np+1][0]=t1; bH[2*np+1][1]=t3;
                ldm4(cvsm(sBl+row*LDT+colo), t0,t1,t2,t3);
                bL[2*np][0]=t0; bL[2*np][1]=t2; bL[2*np+1][0]=t1; bL[2*np+1][1]=t3;
            }
#pragma unroll
            for(int mt=0;mt<4;mt++)
#pragma unroll
            for(int nt=0;nt<4;nt++){
                mmabf(acc[mt][nt], aH[mt], bH[nt]);
                mmabf(acc[mt][nt], aH[mt], bL[nt]);
                mmabf(acc[mt][nt], aL[mt], bH[nt]);
            }
        }
        __syncthreads();
    }
#pragma unroll
    for(int mt=0;mt<4;mt++)
#pragma unroll
    for(int nt=0;nt<4;nt++){
        int n0=colBase+wn*32+nt*8+((lane&3)<<1);
        float b0=0.f,b1=0.f;
        if(bias){ b0=bias[n0]; b1=bias[n0+1]; }
#pragma unroll
        for(int hh=0;hh<2;hh++){
            long row=rowBase+wm*64+mt*16+(lane>>2)+hh*8;
            float v0=acc[mt][nt][2*hh]+b0, v1=acc[mt][nt][2*hh+1]+b1;
            if(EPI==1){ v0*=1.f/(1.f+__expf(-v0)); v1*=1.f/(1.f+__expf(-v1)); }
            if(EPI==2){ v0=tanhf(v0); v1=tanhf(v1); }
            long o=row*(long)N+n0;
            if(C32){ float2 f; f.x=v0; f.y=v1; *(float2*)(C32+o)=f; }
            if(Ch){
                bf16 h0,l0,h1,l1; split2(v0,h0,l0); split2(v1,h1,l1);
                __nv_bfloat162 ph,pl; ph.x=h0; ph.y=h1; pl.x=l0; pl.y=l1;
                *(__nv_bfloat162*)(Ch+o)=ph; *(__nv_bfloat162*)(Cl+o)=pl;
            }
        }
    }
}

__global__ void k_init(const float* __restrict__ x, float* __restrict__ cur,
                       bf16* __restrict__ ch, bf16* __restrict__ cl){
    long idx=(long)blockIdx.x*256+threadIdx.x;
    float v=x[idx]; cur[idx]=v;
    bf16 h,l; split2(v,h,l); ch[idx]=h; cl[idx]=l;
}

__global__ void k_split_t(const float* __restrict__ W, bf16* __restrict__ oh, bf16* __restrict__ ol,
                          int K, int N, int do_tanh, long total){
    long idx=(long)blockIdx.x*256+threadIdx.x;
    if(idx>=total) return;
    int k=(int)(idx/N), n=(int)(idx%N);
    float v=W[idx]; if(do_tanh) v=tanhf(v);
    bf16 h,l; split2(v,h,l);
    oh[(long)n*K+k]=h; ol[(long)n*K+k]=l;
}

__global__ void k_attn_fuse(const float* __restrict__ wqkv, const float* __restrict__ bqkv,
                            const float* __restrict__ wo, const float* __restrict__ bo,
                            float* __restrict__ wf, float* __restrict__ battn){
    int i=blockIdx.y;
    int idx=blockIdx.x*256+threadIdx.x;
    int k=idx>>8, n=idx&255;
    const float* Wv=wqkv+(long)i*256*768+512;
    const float* Wo=wo+(long)i*256*256;
    float s=0.f;
    for(int j=0;j<256;j++) s+=Wv[(long)k*768+j]*Wo[(long)j*256+n];
    wf[(long)i*65536+idx]=s;
    if(k==0){
        float sb=bo[i*256+n];
        for(int j=0;j<256;j++) sb+=bqkv[(long)i*768+512+j]*Wo[(long)j*256+n];
        battn[i*256+n]=sb;
    }
}

__global__ void k_lin(const float* __restrict__ gp, float* __restrict__ lin){
    int idx=blockIdx.x*256+threadIdx.x;
    const float* p=gp+(long)idx*6;
    lin[idx]=sinf(p[0])+cosf(p[1])+tanhf(p[2]);
}

__global__ void k_ln_gelu(const float* __restrict__ h, const float* __restrict__ w, const float* __restrict__ b,
                          bf16* __restrict__ oh, bf16* __restrict__ ol){
    int row=blockIdx.x*8+(threadIdx.x>>5);
    int lane=threadIdx.x&31;
    const float* hr=h+(long)row*768;
    float v[24]; float s=0.f,s2=0.f;
#pragma unroll
    for(int j=0;j<24;j++){ float x=hr[lane+32*j]; v[j]=x; s+=x; s2+=x*x; }
#pragma unroll
    for(int o=16;o;o>>=1){ s+=__shfl_xor_sync(0xffffffffu,s,o); s2+=__shfl_xor_sync(0xffffffffu,s2,o); }
    float mu=s*(1.f/768.f);
    float var=s2*(1.f/768.f)-mu*mu;
    float inv=rsqrtf(var+1e-5f);
    long base=(long)row*768;
#pragma unroll
    for(int j=0;j<24;j++){
        int q=lane+32*j;
        float y=(v[j]-mu)*inv*w[q]+b[q];
        float g=0.5f*y*(1.f+erff(y*0.70710678118654752f));
        bf16 hh,ll; split2(g,hh,ll);
        oh[base+q]=hh; ol[base+q]=ll;
    }
}

__global__ void k_combine(const float* __restrict__ tmp, const float* __restrict__ ent,
                          const float* __restrict__ gp_layer, const float* __restrict__ lin_layer,
                          float* __restrict__ c2, bf16* __restrict__ c2h, bf16* __restrict__ c2l){
    long idx=(long)blockIdx.x*256+threadIdx.x;
    int q=(int)(idx&255);
    float t=tmp[idx];
    float p3=gp_layer[q*6+3], p4=gp_layer[q*6+4], p5=gp_layer[q*6+5];
    float gate=(lin_layer[q]*t + 0.5f*sinf(p3*t+p4) + 0.5f*cosf(p5*t))*0.25f;
    float v=(t + 0.3f*gate + 0.2f*ent[idx])*(1.0f/1.5f);
    c2[idx]=v;
    bf16 h,l; split2(v,h,l); c2h[idx]=h; c2l[idx]=l;
}

__global__ void k_final(const float* __restrict__ c2, const float* __restrict__ nl,
                        float* __restrict__ cur, bf16* __restrict__ ch, bf16* __restrict__ cl,
                        float* __restrict__ outp, float alpha){
    int row=blockIdx.x*8+(threadIdx.x>>5);
    int lane=threadIdx.x&31;
    long base=(long)row*QD;
    float v[8]; float ss=0.f;
#pragma unroll
    for(int j=0;j<8;j++){
        int q=lane+32*j;
        float x=c2[base+q];
        if(nl) x+=0.1f*nl[base+q];
        float y=alpha*x+(1.f-alpha)*cur[base+q];
        v[j]=y; ss+=y*y;
    }
#pragma unroll
    for(int o=16;o;o>>=1) ss+=__shfl_xor_sync(0xffffffffu,ss,o);
    float inv=1.f/(sqrtf(ss)+1e-8f);
#pragma unroll
    for(int j=0;j<8;j++){
        int q=lane+32*j;
        float y=tanhf(v[j]*inv);
        if(outp) outp[base+q]=y;
        else{ cur[base+q]=y; bf16 h,l; split2(y,h,l); ch[base+q]=h; cl[base+q]=l; }
    }
}

static void* symaddr(const void* s){ void* p=nullptr; cudaGetSymbolAddress(&p, s); return p; }

static void gemm(int epi, const bf16* Ah,const bf16* Al,const bf16* Bh,const bf16* Bl,
                 const float* bias, float* C32, bf16* Ch, bf16* Cl, int K,int N){
    dim3 grid(N/128, BATCHN/128);
    if(epi==0)      gemm_k<0><<<grid,256>>>(Ah,Al,Bh,Bl,bias,C32,Ch,Cl,K,N);
    else if(epi==1) gemm_k<1><<<grid,256>>>(Ah,Al,Bh,Bl,bias,C32,Ch,Cl,K,N);
    else            gemm_k<2><<<grid,256>>>(Ah,Al,Bh,Bl,bias,C32,Ch,Cl,K,N);
}

extern "C" void kernel_launch(void* const* d_in, const int* in_sizes, int n_in,
                              void* d_out, int out_size){
    (void)in_sizes;(void)n_in;(void)out_size;
    const float* x   =(const float*)d_in[0];
    const float* d0w1=(const float*)d_in[1];
    const float* d0b1=(const float*)d_in[2];
    const float* lnw =(const float*)d_in[3];
    const float* lnb =(const float*)d_in[4];
    const float* d0w2=(const float*)d_in[5];
    const float* d0b2=(const float*)d_in[6];
    const float* d1w1=(const float*)d_in[7];
    const float* d1b1=(const float*)d_in[8];
    const float* d1w2=(const float*)d_in[9];
    const float* d1b2=(const float*)d_in[10];
    const float* wqkv=(const float*)d_in[11];
    const float* bqkv=(const float*)d_in[12];
    const float* wo  =(const float*)d_in[13];
    const float* bo  =(const float*)d_in[14];
    const float* gp  =(const float*)d_in[15];
    const float* ent =(const float*)d_in[16];
    const float* nw1 =(const float*)d_in[17];
    const float* nb1 =(const float*)d_in[18];
    const float* nw2 =(const float*)d_in[19];
    const float* nb2 =(const float*)d_in[20];

    float* h32  =(float*)symaddr(g_h32);
    float* tmp32=(float*)symaddr(g_tmp32);
    float* ent32=(float*)symaddr(g_ent32);
    float* c232 =(float*)symaddr(g_c232);
    float* nl32 =(float*)symaddr(g_nl32);
    float* cur32=(float*)symaddr(g_cur32);
    bf16* curh=(bf16*)symaddr(g_curh); bf16* curl=(bf16*)symaddr(g_curl);
    bf16* hh_ =(bf16*)symaddr(g_hh);   bf16* hl_ =(bf16*)symaddr(g_hl);
    bf16* tmph=(bf16*)symaddr(g_tmph); bf16* tmpl=(bf16*)symaddr(g_tmpl);
    bf16* c2h =(bf16*)symaddr(g_c2h);  bf16* c2l =(bf16*)symaddr(g_c2l);
    bf16* wh  =(bf16*)symaddr(g_w_h);  bf16* wl  =(bf16*)symaddr(g_w_l);
    float* wf   =(float*)symaddr(g_wf);
    float* battn=(float*)symaddr(g_battn);
    float* lin  =(float*)symaddr(g_lin);

    const long O_D0W1=0, O_D0W2=589824, O_D1W1=1179648, O_D1W2=1572864;
    const long O_ATT=1966080, O_TENT=2097152, O_NW1=2621440, O_NW2=2883584;

    for(int i=0;i<3;i++){
        k_split_t<<<768,256>>>(d0w1+(long)i*196608, wh+O_D0W1+(long)i*196608, wl+O_D0W1+(long)i*196608, 256,768,0,196608);
        k_split_t<<<768,256>>>(d0w2+(long)i*196608, wh+O_D0W2+(long)i*196608, wl+O_D0W2+(long)i*196608, 768,256,0,196608);
        k_split_t<<<512,256>>>(d1w1+(long)i*131072, wh+O_D1W1+(long)i*131072, wl+O_D1W1+(long)i*131072, 256,512,0,131072);
        k_split_t<<<512,256>>>(d1w2+(long)i*131072, wh+O_D1W2+(long)i*131072, wl+O_D1W2+(long)i*131072, 512,256,0,131072);
    }
    k_attn_fuse<<<dim3(256,2),256>>>(wqkv,bqkv,wo,bo,wf,battn);
    for(int i=0;i<2;i++)
        k_split_t<<<256,256>>>(wf+(long)i*65536, wh+O_ATT+(long)i*65536, wl+O_ATT+(long)i*65536, 256,256,0,65536);
    for(int li=0;li<8;li++)
        k_split_t<<<256,256>>>(ent+(long)li*65536, wh+O_TENT+(long)li*65536, wl+O_TENT+(long)li*65536, 256,256,1,65536);
    for(int j=0;j<4;j++){
        k_split_t<<<256,256>>>(nw1+(long)j*65536, wh+O_NW1+(long)j*65536, wl+O_NW1+(long)j*65536, 256,256,0,65536);
        k_split_t<<<256,256>>>(nw2+(long)j*65536, wh+O_NW2+(long)j*65536, wl+O_NW2+(long)j*65536, 256,256,0,65536);
    }
    k_lin<<<8,256>>>(gp, lin);
    k_init<<<BATCHN*QD/256,256>>>(x, cur32, curh, curl);

    for(int li=0;li<8;li++){
        int t=li%3;
        if(t==0){
            int i=li/3;
            gemm(0, curh,curl, wh+O_D0W1+(long)i*196608, wl+O_D0W1+(long)i*196608,
                 d0b1+(long)i*768, h32, nullptr,nullptr, 256,768);
            k_ln_gelu<<<BATCHN/8,256>>>(h32, lnw+(long)i*768, lnb+(long)i*768, hh_, hl_);
            gemm(0, hh_,hl_, wh+O_D0W2+(long)i*196608, wl+O_D0W2+(long)i*196608,
                 d0b2+(long)i*256, tmp32, tmph,tmpl, 768,256);
        } else if(t==1){
            int i=(li-1)/3;
            gemm(1, curh,curl, wh+O_D1W1+(long)i*131072, wl+O_D1W1+(long)i*131072,
                 d1b1+(long)i*512, nullptr, hh_,hl_, 256,512);
            gemm(0, hh_,hl_, wh+O_D1W2+(long)i*131072, wl+O_D1W2+(long)i*131072,
                 d1b2+(long)i*256, tmp32, tmph,tmpl, 512,256);
        } else {
            int i=(li-2)/3;
            gemm(0, curh,curl, wh+O_ATT+(long)i*65536, wl+O_ATT+(long)i*65536,
                 battn+(long)i*256, tmp32, tmph,tmpl, 256,256);
        }
        // entangled = tmp @ tanh(ent[li])
        gemm(0, tmph,tmpl, wh+O_TENT+(long)li*65536, wl+O_TENT+(long)li*65536,
             nullptr, ent32, nullptr,nullptr, 256,256);
        k_combine<<<BATCHN*QD/256,256>>>(tmp32, ent32, gp+(long)li*256*6, lin+(long)li*256,
                                         c232, c2h, c2l);
        const float* nlptr=nullptr;
        if(li&1){
            int j=li/2;
            gemm(2, c2h,c2l, wh+O_NW1+(long)j*65536, wl+O_NW1+(long)j*65536,
                 nb1+(long)j*256, nullptr, hh_,hl_, 256,256);
            gemm(0, hh_,hl_, wh+O_NW2+(long)j*65536, wl+O_NW2+(long)j*65536,
                 nb2+(long)j*256, nl32, nullptr,nullptr, 256,256);
            nlptr=nl32;
        }
        float alpha=(li<4)?0.8f:0.6f;
        float* outp=(li==7)?(float*)d_out:nullptr;
        k_final<<<BATCHN/8,256>>>(c232, nlptr, cur32, curh, curl, outp, alpha);
    }
}